// round 2
// baseline (speedup 1.0000x reference)
#include <cuda_runtime.h>

#define NV   32768
#define KC   8192
#define DIMV 64
#define ND   (NV * DIMV)

#define ROWS    128
#define CTILE   64
#define NTILES  (KC / CTILE)
#define ESTRIDE 68   // 64 + 4 floats pad: with strided col mapping, e-LDS.128 is conflict-free
#define SMEM_FLOATS (ROWS * DIMV + CTILE * ESTRIDE)

__device__ float g_esq[KC];
__device__ float g_block_sums[NV / ROWS];

__device__ __forceinline__ void ffma2(unsigned long long &d,
                                      unsigned long long a,
                                      unsigned long long b) {
    // packed fp32x2 FMA (Blackwell): two fp32 MACs per instruction
    asm("fma.rn.f32x2 %0, %1, %2, %0;" : "+l"(d) : "l"(a), "l"(b));
}

// Kernel 1: per-code squared norms
__global__ void vq_prep(const float* __restrict__ cb) {
    int k = blockIdx.x * blockDim.x + threadIdx.x;
    if (k < KC) {
        const float4* row = reinterpret_cast<const float4*>(cb + (size_t)k * DIMV);
        float s = 0.f;
        #pragma unroll
        for (int j = 0; j < 16; j++) {
            float4 v = row[j];
            s += v.x * v.x + v.y * v.y + v.z * v.z + v.w * v.w;
        }
        g_esq[k] = s;
    }
}

// Kernel 2: fused distance-GEMM + argmin + gather + quantized write + loss partials
__global__ __launch_bounds__(256, 1) void vq_main(
    const float* __restrict__ z, const float* __restrict__ cb,
    float* __restrict__ out, int out_size)
{
    extern __shared__ float sm[];
    float* z_s = sm;                   // ROWS * 64 floats
    float* e_s = sm + ROWS * DIMV;     // CTILE * ESTRIDE floats

    const int tid  = threadIdx.x;
    const int row0 = blockIdx.x * ROWS;

    // Load z tile (coalesced float4): 128 rows x 64 floats
    {
        const float4* zg = reinterpret_cast<const float4*>(z + (size_t)row0 * DIMV);
        float4* zs = reinterpret_cast<float4*>(z_s);
        #pragma unroll
        for (int i = 0; i < 8; i++) zs[tid + 256 * i] = zg[tid + 256 * i];
    }

    const int col_t  = tid & 15;   // 16 column-threads share the same 8 rows
    const int row_t  = tid >> 4;   // 16 row groups of 8 rows
    const int r_base = row_t * 8;

    float best[8];
    int   bidx[8];
    #pragma unroll
    for (int r = 0; r < 8; r++) { best[r] = 3.4e38f; bidx[r] = 0; }

    // Prefetch codebook tile 0 into registers
    const float4* cg = reinterpret_cast<const float4*>(cb);
    float4 stage[4];
    #pragma unroll
    for (int i = 0; i < 4; i++) stage[i] = cg[tid + 256 * i];

    for (int t = 0; t < NTILES; t++) {
        // Stage -> smem with padded stride
        #pragma unroll
        for (int i = 0; i < 4; i++) {
            int f  = tid + 256 * i;   // float4 index within tile (0..1023)
            int er = f >> 4;          // entry row 0..63
            int ed = f & 15;          // float4 within row
            *reinterpret_cast<float4*>(&e_s[er * ESTRIDE + ed * 4]) = stage[i];
        }
        __syncthreads();

        // Prefetch next tile (overlaps compute)
        if (t + 1 < NTILES) {
            const float4* ng = cg + (size_t)(t + 1) * 1024;
            #pragma unroll
            for (int i = 0; i < 4; i++) stage[i] = ng[tid + 256 * i];
        }

        float hesq[4];
        #pragma unroll
        for (int cc = 0; cc < 4; cc++)
            hesq[cc] = 0.5f * g_esq[t * CTILE + col_t + 16 * cc];

        unsigned long long acc[8][4];
        #pragma unroll
        for (int r = 0; r < 8; r++)
            #pragma unroll
            for (int c = 0; c < 4; c++) acc[r][c] = 0ull;

        // D reduction: f32x2-packed, 4 d-values per iteration
        #pragma unroll 4
        for (int d4 = 0; d4 < DIMV; d4 += 4) {
            ulonglong2 ev[4];
            #pragma unroll
            for (int cc = 0; cc < 4; cc++)
                ev[cc] = *reinterpret_cast<const ulonglong2*>(
                    &e_s[(col_t + 16 * cc) * ESTRIDE + d4]);
            ulonglong2 zv[8];
            #pragma unroll
            for (int r = 0; r < 8; r++)
                zv[r] = *reinterpret_cast<const ulonglong2*>(
                    &z_s[(r_base + r) * DIMV + d4]);
            #pragma unroll
            for (int r = 0; r < 8; r++)
                #pragma unroll
                for (int cc = 0; cc < 4; cc++) {
                    ffma2(acc[r][cc], zv[r].x, ev[cc].x);
                    ffma2(acc[r][cc], zv[r].y, ev[cc].y);
                }
        }

        // Scores + running argmin (ascending entry index; strict < => first-min tiebreak)
        #pragma unroll
        for (int cc = 0; cc < 4; cc++) {
            int ci = t * CTILE + col_t + 16 * cc;
            #pragma unroll
            for (int r = 0; r < 8; r++) {
                unsigned lo = (unsigned)(acc[r][cc] & 0xffffffffull);
                unsigned hi = (unsigned)(acc[r][cc] >> 32);
                float dot = __uint_as_float(lo) + __uint_as_float(hi);
                float s = hesq[cc] - dot;
                if (s < best[r]) { best[r] = s; bidx[r] = ci; }
            }
        }
        __syncthreads();  // before e_s is overwritten next tile
    }

    // Reduce argmin across the 16 column-threads sharing each row set
    #pragma unroll
    for (int r = 0; r < 8; r++) {
        float s = best[r];
        int   i = bidx[r];
        #pragma unroll
        for (int off = 8; off >= 1; off >>= 1) {
            float os = __shfl_xor_sync(0xffffffffu, s, off);
            int   oi = __shfl_xor_sync(0xffffffffu, i, off);
            if (os < s || (os == s && oi < i)) { s = os; i = oi; }
        }
        best[r] = s; bidx[r] = i;
    }

    // col_t==0 threads: gather codebook rows, write quantized + index, loss partial
    float lsum = 0.f;
    if (col_t == 0) {
        #pragma unroll
        for (int r = 0; r < 8; r++) {
            int grow = row0 + r_base + r;
            int k    = bidx[r];
            const float4* crow = reinterpret_cast<const float4*>(cb + (size_t)k * DIMV);
            const float4* zrow = reinterpret_cast<const float4*>(&z_s[(r_base + r) * DIMV]);
            float4* qrow = reinterpret_cast<float4*>(out + (size_t)grow * DIMV);
            #pragma unroll
            for (int j = 0; j < 16; j++) {
                float4 e  = crow[j];
                float4 zz = zrow[j];
                qrow[j] = e;  // straight-through: quantized == codebook[idx]
                float dx = zz.x - e.x, dy = zz.y - e.y;
                float dz = zz.z - e.z, dw = zz.w - e.w;
                lsum += dx * dx + dy * dy + dz * dz + dw * dw;
            }
            if (out_size >= ND + 2 + NV)
                out[ND + 2 + grow] = (float)k;
        }
    }

    // Deterministic block loss partial
    #pragma unroll
    for (int off = 16; off >= 1; off >>= 1)
        lsum += __shfl_xor_sync(0xffffffffu, lsum, off);
    __syncthreads();
    if ((tid & 31) == 0) e_s[tid >> 5] = lsum;
    __syncthreads();
    if (tid == 0) {
        float b = 0.f;
        #pragma unroll
        for (int w = 0; w < 8; w++) b += e_s[w];
        g_block_sums[blockIdx.x] = b;
    }
}

// Kernel 3: deterministic final loss reduction (vq_loss == commitment_loss)
__global__ void vq_finalize(float* __restrict__ out, int out_size) {
    if (out_size >= ND + 2) {
        float s = 0.f;
        for (int i = 0; i < NV / ROWS; i++) s += g_block_sums[i];
        float m = s / (float)ND;
        out[ND]     = m;  // vq_loss
        out[ND + 1] = m;  // commitment_loss
    }
}

extern "C" void kernel_launch(void* const* d_in, const int* in_sizes, int n_in,
                              void* d_out, int out_size) {
    const float* a = (const float*)d_in[0];
    const float* b = (const float*)d_in[1];
    const float* z;
    const float* cb;
    if (in_sizes[0] == NV * DIMV) { z = a; cb = b; }
    else                          { z = b; cb = a; }
    float* out = (float*)d_out;

    size_t smem = SMEM_FLOATS * sizeof(float);  // 50176 B
    cudaFuncSetAttribute(vq_main, cudaFuncAttributeMaxDynamicSharedMemorySize, (int)smem);

    vq_prep<<<KC / 256, 256>>>(cb);
    vq_main<<<NV / ROWS, 256, smem>>>(z, cb, out, out_size);
    vq_finalize<<<1, 1>>>(out, out_size);
}

// round 4
// speedup vs baseline: 1.0971x; 1.0971x over previous
#include <cuda_runtime.h>
#include <cstdint>

#define NV   32768
#define KC   8192
#define DIMV 64
#define ND   (NV * DIMV)

#define ROWS    32                  // z rows per block
#define NBLK    (NV / ROWS)         // 1024 blocks
#define CTILE   512                 // codebook entries per tile
#define NTILES  (KC / CTILE)        // 16
#define NCHUNK  (NTILES * 2)        // 32 half-D chunks
#define ZS      66                  // z smem stride (floats): bank-spacing 2, 8B aligned
#define ES      36                  // e smem stride (floats): bank-spacing 4, 16B aligned
#define CHUNK_FLOATS (CTILE * ES)   // 18432 floats = 73728 B per buffer

__device__ float g_esq[KC];
__device__ float g_block_sums[NBLK];

__device__ __forceinline__ void ffma2(unsigned long long &d,
                                      unsigned long long a,
                                      unsigned long long b) {
    asm("fma.rn.f32x2 %0, %1, %2, %0;" : "+l"(d) : "l"(a), "l"(b));
}

__device__ __forceinline__ void cp16(float* dst_s, const float* src_g) {
    uint32_t d = (uint32_t)__cvta_generic_to_shared(dst_s);
    asm volatile("cp.async.cg.shared.global [%0], [%1], 16;" :: "r"(d), "l"(src_g));
}

// Kernel 1: per-code squared norms (fp32 exact)
__global__ void vq_prep(const float* __restrict__ cb) {
    int k = blockIdx.x * blockDim.x + threadIdx.x;
    if (k < KC) {
        const float4* row = reinterpret_cast<const float4*>(cb + (size_t)k * DIMV);
        float s = 0.f;
        #pragma unroll
        for (int j = 0; j < 16; j++) {
            float4 v = row[j];
            s += v.x * v.x + v.y * v.y + v.z * v.z + v.w * v.w;
        }
        g_esq[k] = s;
    }
}

// Kernel 2: fused distance-GEMM + argmin + gather + losses
__global__ __launch_bounds__(256, 1) void vq_main(
    const float* __restrict__ z, const float* __restrict__ cb,
    float* __restrict__ out, int out_size)
{
    extern __shared__ float sm[];
    float* e_buf0 = sm;
    float* e_buf1 = sm + CHUNK_FLOATS;
    float* z_s    = sm + 2 * CHUNK_FLOATS;            // ROWS*ZS = 2112 floats
    float2* red   = reinterpret_cast<float2*>(z_s + ROWS * ZS); // 8*32 float2

    const int tid   = threadIdx.x;
    const int lane  = tid & 31;
    const int warp  = tid >> 5;
    const int row_t = lane & 3;        // 4 row-threads per warp
    const int csub  = lane >> 2;       // 8 col-subthreads per warp
    const int ct    = warp * 8 + csub; // block col-thread 0..63
    const int row0  = blockIdx.x * ROWS;

    // Load z tile: 32 rows x 64 floats -> stride-66 smem (float2 granularity)
    {
        const float2* zg = reinterpret_cast<const float2*>(z + (size_t)row0 * DIMV);
        #pragma unroll
        for (int i = 0; i < 4; i++) {
            int f  = tid + 256 * i;     // 0..1023 float2 slots
            int r  = f >> 5;            // row 0..31
            int d2 = f & 31;            // float2 within row
            *reinterpret_cast<float2*>(&z_s[r * ZS + d2 * 2]) = zg[f];
        }
    }

    // Preload chunk 0
    {
        #pragma unroll
        for (int n = 0; n < 16; n++) {
            int q = tid + 256 * n;      // 0..4095 16B quads
            int code = q >> 3;
            int dd   = q & 7;
            cp16(e_buf0 + code * ES + dd * 4, cb + (size_t)code * DIMV + dd * 4);
        }
        asm volatile("cp.async.commit_group;" ::: "memory");
    }

    float best[8];
    int   bidx[8];
    #pragma unroll
    for (int k = 0; k < 8; k++) { best[k] = 3.4e38f; bidx[k] = 0; }

    float hesq[8];
    unsigned long long acc[8][8];

    for (int q = 0; q < NCHUNK; q++) {
        asm volatile("cp.async.wait_group 0;" ::: "memory");
        __syncthreads();

        // Issue next chunk into the other buffer (readers of it finished last iter)
        if (q + 1 < NCHUNK) {
            float* nb = ((q + 1) & 1) ? e_buf1 : e_buf0;
            int nt = (q + 1) >> 1, nh = (q + 1) & 1;
            const float* src_base = cb + (size_t)nt * CTILE * DIMV + nh * 32;
            #pragma unroll
            for (int n = 0; n < 16; n++) {
                int qq = tid + 256 * n;
                int code = qq >> 3;
                int dd   = qq & 7;
                cp16(nb + code * ES + dd * 4, src_base + (size_t)code * DIMV + dd * 4);
            }
            asm volatile("cp.async.commit_group;" ::: "memory");
        }

        const float* eb = (q & 1) ? e_buf1 : e_buf0;
        const int t = q >> 1, h = q & 1;

        if (h == 0) {
            #pragma unroll
            for (int j = 0; j < 8; j++)
                hesq[j] = 0.5f * g_esq[t * CTILE + ct + 64 * j];
            #pragma unroll
            for (int k = 0; k < 8; k++)
                #pragma unroll
                for (int j = 0; j < 8; j++) acc[k][j] = 0ull;
        }

        const float* zb = z_s + h * 32;

        #pragma unroll 4
        for (int d2 = 0; d2 < 16; d2++) {
            unsigned long long ev[8];
            #pragma unroll
            for (int j = 0; j < 8; j++)
                ev[j] = *reinterpret_cast<const unsigned long long*>(
                    eb + (ct + 64 * j) * ES + d2 * 2);
            unsigned long long zv[8];
            #pragma unroll
            for (int k = 0; k < 8; k++)
                zv[k] = *reinterpret_cast<const unsigned long long*>(
                    zb + (row_t + 4 * k) * ZS + d2 * 2);
            #pragma unroll
            for (int k = 0; k < 8; k++)
                #pragma unroll
                for (int j = 0; j < 8; j++)
                    ffma2(acc[k][j], zv[k], ev[j]);
        }

        if (h == 1) {
            // Scores: 0.5||e||^2 - z.e ; ascending ci + strict < => first-min tiebreak
            #pragma unroll
            for (int j = 0; j < 8; j++) {
                int ci = t * CTILE + ct + 64 * j;
                float h2 = hesq[j];
                #pragma unroll
                for (int k = 0; k < 8; k++) {
                    float lo = __uint_as_float((unsigned)(acc[k][j] & 0xffffffffull));
                    float hi = __uint_as_float((unsigned)(acc[k][j] >> 32));
                    float s = h2 - (lo + hi);
                    if (s < best[k]) { best[k] = s; bidx[k] = ci; }
                }
            }
        }
    }

    // Reduce over the 8 col-subthreads within each warp (lanes xor 4,8,16 keep row_t)
    #pragma unroll
    for (int k = 0; k < 8; k++) {
        float s = best[k];
        int   i = bidx[k];
        #pragma unroll
        for (int off = 4; off <= 16; off <<= 1) {
            float os = __shfl_xor_sync(0xffffffffu, s, off);
            int   oi = __shfl_xor_sync(0xffffffffu, i, off);
            if (os < s || (os == s && oi < i)) { s = os; i = oi; }
        }
        best[k] = s; bidx[k] = i;
    }

    if (csub == 0) {
        #pragma unroll
        for (int k = 0; k < 8; k++)
            red[warp * 32 + row_t + 4 * k] =
                make_float2(best[k], __int_as_float(bidx[k]));
    }
    __syncthreads();

    float lsum = 0.f;
    if (warp == 0) {
        int r = lane;   // one lane per row
        float s = 3.4e38f; int i = 0;
        #pragma unroll
        for (int w = 0; w < 8; w++) {
            float2 p = red[w * 32 + r];
            int pi = __float_as_int(p.y);
            if (p.x < s || (p.x == s && pi < i)) { s = p.x; i = pi; }
        }
        // Gather codebook row, write quantized + index, exact fp32 loss partial
        const float4* crow = reinterpret_cast<const float4*>(cb + (size_t)i * DIMV);
        float4* qrow = reinterpret_cast<float4*>(out + (size_t)(row0 + r) * DIMV);
        #pragma unroll
        for (int j4 = 0; j4 < 16; j4++) {
            float4 e = crow[j4];
            float2 za = *reinterpret_cast<const float2*>(&z_s[r * ZS + j4 * 4]);
            float2 zb2 = *reinterpret_cast<const float2*>(&z_s[r * ZS + j4 * 4 + 2]);
            qrow[j4] = e;
            float dx = za.x - e.x, dy = za.y - e.y;
            float dz = zb2.x - e.z, dw = zb2.y - e.w;
            lsum += dx * dx + dy * dy + dz * dz + dw * dw;
        }
        if (out_size >= ND + 2 + NV)
            out[ND + 2 + row0 + r] = (float)i;

        #pragma unroll
        for (int off = 16; off >= 1; off >>= 1)
            lsum += __shfl_xor_sync(0xffffffffu, lsum, off);
        if (lane == 0) g_block_sums[blockIdx.x] = lsum;
    }
}

// Kernel 3: deterministic final loss reduction (vq_loss == commitment_loss)
__global__ void vq_finalize(float* __restrict__ out, int out_size) {
    __shared__ float ws[8];
    int tid = threadIdx.x;
    float s = 0.f;
    #pragma unroll
    for (int i = 0; i < NBLK / 256; i++) s += g_block_sums[tid + 256 * i];
    #pragma unroll
    for (int off = 16; off >= 1; off >>= 1)
        s += __shfl_xor_sync(0xffffffffu, s, off);
    if ((tid & 31) == 0) ws[tid >> 5] = s;
    __syncthreads();
    if (tid == 0) {
        float b = 0.f;
        #pragma unroll
        for (int w = 0; w < 8; w++) b += ws[w];
        float m = b / (float)ND;
        if (out_size >= ND + 2) {
            out[ND]     = m;  // vq_loss
            out[ND + 1] = m;  // commitment_loss
        }
    }
}

extern "C" void kernel_launch(void* const* d_in, const int* in_sizes, int n_in,
                              void* d_out, int out_size) {
    const float* a = (const float*)d_in[0];
    const float* b = (const float*)d_in[1];
    const float* z;
    const float* cb;
    if (in_sizes[0] == NV * DIMV) { z = a; cb = b; }
    else                          { z = b; cb = a; }
    float* out = (float*)d_out;

    size_t smem = (2 * CHUNK_FLOATS + ROWS * ZS) * sizeof(float)
                + 8 * 32 * sizeof(float2);            // ~158 KB
    cudaFuncSetAttribute(vq_main, cudaFuncAttributeMaxDynamicSharedMemorySize, (int)smem);

    vq_prep<<<KC / 128, 128>>>(cb);
    vq_main<<<NBLK, 256, smem>>>(z, cb, out, out_size);
    vq_finalize<<<1, 256>>>(out, out_size);
}